// round 2
// baseline (speedup 1.0000x reference)
#include <cuda_runtime.h>
#include <cstdint>

typedef unsigned long long u64;

__device__ float g_u_tgt;

// Compute u(target) = MLP(6.2562059, 6.2562059) once per launch.
__global__ void utgt_kernel(const float* __restrict__ W1, const float* __restrict__ b1,
                            const float* __restrict__ W2, const float* __restrict__ b2,
                            const float* __restrict__ W3, const float* __restrict__ b3) {
    __shared__ float h1[64];
    __shared__ float part[64];
    int t = threadIdx.x;  // 64 threads
    const float tt = 6.2562059f;
    float h = fmaf(W1[2 * t], tt, fmaf(W1[2 * t + 1], tt, b1[t]));
    h1[t] = fmaxf(h, 0.f);
    __syncthreads();
    float acc = b2[t];
#pragma unroll
    for (int k = 0; k < 64; k++) acc = fmaf(W2[t * 64 + k], h1[k], acc);
    part[t] = W3[t] * fmaxf(acc, 0.f);
    __syncthreads();
    if (t == 0) {
        float s = b3[0];
#pragma unroll
        for (int k = 0; k < 64; k++) s += part[k];
        g_u_tgt = s;
    }
}

__device__ __forceinline__ void hill_out(float* __restrict__ out, int n, int i,
                                         float xv, float yv, float u) {
    float xs = xv * 0.1f, ys = yv * 0.1f;
    float x2 = xs * xs, y2 = ys * ys;
    float ivx = 1.f / (0.25f + x2);
    float ivy = 1.f / (0.25f + y2);
    float hx = x2 * ivx, hy = y2 * ivy;
    float gx = 0.25f * ivx, gy = 0.25f * ivy;
    float dx = 10.f * (hx + 0.2f * gy - 1.1f * xs + u * hx);
    float dy = 10.f * (hy + 0.2f * gx - 1.1f * ys);
    out[i] = dx;
    out[n + i] = dy;
    out[2 * n + i] = -dx;
    out[3 * n + i] = -dy;
}

__global__ void __launch_bounds__(128) netc_kernel(
    const float* __restrict__ x, const float* __restrict__ y,
    const float* __restrict__ ex, const float* __restrict__ ey,
    const float* __restrict__ W1, const float* __restrict__ b1,
    const float* __restrict__ W2, const float* __restrict__ b2,
    const float* __restrict__ W3, const float* __restrict__ b3,
    float* __restrict__ out, int n, int half) {
    __shared__ u64 w2d[64 * 64];   // W2 duplicated (w,w) pairs: 32 KB
    __shared__ u64 b2d[64];
    __shared__ float w1s[128];
    __shared__ float b1s[64];
    __shared__ float w3s[64];

    int tid = threadIdx.x;
    for (int i = tid; i < 4096; i += 128) {
        unsigned w = __float_as_uint(W2[i]);
        w2d[i] = ((u64)w << 32) | (u64)w;
    }
    if (tid < 64) {
        unsigned v = __float_as_uint(b2[tid]);
        b2d[tid] = ((u64)v << 32) | (u64)v;
        b1s[tid] = b1[tid];
        w3s[tid] = W3[tid];
    }
    w1s[tid] = W1[tid];  // W1 has 64*2 = 128 elements, blockDim == 128
    __syncthreads();

    int i0 = blockIdx.x * 128 + tid;
    if (i0 >= half) return;
    int i1 = i0 + half;
    bool has1 = (i1 < n);
    int i1c = has1 ? i1 : i0;

    float x0 = x[i0], y0 = y[i0];
    float a0 = x0 + ex[i0], c0 = y0 + ey[i0];
    float x1 = x[i1c], y1 = y[i1c];
    float a1 = x1 + ex[i1c], c1 = y1 + ey[i1c];

    // Layer 1: h1 packed as (elem0 in lo, elem1 in hi), kept in registers.
    u64 h1p[64];
#pragma unroll
    for (int k = 0; k < 64; k++) {
        float wA = w1s[2 * k], wB = w1s[2 * k + 1], bb = b1s[k];
        float h0 = fmaxf(fmaf(wA, a0, fmaf(wB, c0, bb)), 0.f);
        float h1 = fmaxf(fmaf(wA, a1, fmaf(wB, c1, bb)), 0.f);
        h1p[k] = ((u64)__float_as_uint(h1) << 32) | (u64)__float_as_uint(h0);
    }

    // Shared-state-space 32-bit base addresses for PTX LDS.
    unsigned w2addr = (unsigned)__cvta_generic_to_shared(w2d);
    unsigned b2addr = (unsigned)__cvta_generic_to_shared(b2d);

    // Layer 2 + 3: per output neuron j, packed dot over k.
    // 128-bit shared loads (2 duplicated pairs each) halve LDS issue count.
    float o0 = 0.f, o1 = 0.f;
#pragma unroll 2
    for (int j = 0; j < 64; j++) {
        unsigned wrow = w2addr + (j << 9);  // 64 pairs * 8 B per row
        u64 a0q, a1q = 0ull, a2q = 0ull, a3q = 0ull;
        asm("ld.shared.b64 %0, [%1];" : "=l"(a0q) : "r"(b2addr + (j << 3)));
#pragma unroll
        for (int k = 0; k < 64; k += 8) {
            u64 w0, w1v, w2v, w3v, w4, w5, w6, w7;
            unsigned a = wrow + (k << 3);
            asm("ld.shared.v2.b64 {%0, %1}, [%2];"      : "=l"(w0), "=l"(w1v) : "r"(a));
            asm("ld.shared.v2.b64 {%0, %1}, [%2+16];"   : "=l"(w2v), "=l"(w3v) : "r"(a));
            asm("ld.shared.v2.b64 {%0, %1}, [%2+32];"   : "=l"(w4), "=l"(w5) : "r"(a));
            asm("ld.shared.v2.b64 {%0, %1}, [%2+48];"   : "=l"(w6), "=l"(w7) : "r"(a));
            asm("fma.rn.f32x2 %0, %1, %2, %0;" : "+l"(a0q) : "l"(w0),  "l"(h1p[k + 0]));
            asm("fma.rn.f32x2 %0, %1, %2, %0;" : "+l"(a1q) : "l"(w1v), "l"(h1p[k + 1]));
            asm("fma.rn.f32x2 %0, %1, %2, %0;" : "+l"(a2q) : "l"(w2v), "l"(h1p[k + 2]));
            asm("fma.rn.f32x2 %0, %1, %2, %0;" : "+l"(a3q) : "l"(w3v), "l"(h1p[k + 3]));
            asm("fma.rn.f32x2 %0, %1, %2, %0;" : "+l"(a0q) : "l"(w4),  "l"(h1p[k + 4]));
            asm("fma.rn.f32x2 %0, %1, %2, %0;" : "+l"(a1q) : "l"(w5),  "l"(h1p[k + 5]));
            asm("fma.rn.f32x2 %0, %1, %2, %0;" : "+l"(a2q) : "l"(w6),  "l"(h1p[k + 6]));
            asm("fma.rn.f32x2 %0, %1, %2, %0;" : "+l"(a3q) : "l"(w7),  "l"(h1p[k + 7]));
        }
        asm("add.rn.f32x2 %0, %0, %1;" : "+l"(a0q) : "l"(a1q));
        asm("add.rn.f32x2 %0, %0, %1;" : "+l"(a2q) : "l"(a3q));
        asm("add.rn.f32x2 %0, %0, %1;" : "+l"(a0q) : "l"(a2q));
        float h0 = __uint_as_float((unsigned)(a0q & 0xffffffffu));
        float h1v = __uint_as_float((unsigned)(a0q >> 32));
        float w3 = w3s[j];
        o0 = fmaf(w3, fmaxf(h0, 0.f), o0);
        o1 = fmaf(w3, fmaxf(h1v, 0.f), o1);
    }

    float bias3 = b3[0];
    float ut = g_u_tgt;
    float u0 = o0 + bias3 - ut;
    float u1 = o1 + bias3 - ut;

    hill_out(out, n, i0, x0, y0, u0);
    if (has1) hill_out(out, n, i1, x1, y1, u1);
}

extern "C" void kernel_launch(void* const* d_in, const int* in_sizes, int n_in,
                              void* d_out, int out_size) {
    const float* x  = (const float*)d_in[0];
    const float* y  = (const float*)d_in[1];
    const float* ex = (const float*)d_in[2];
    const float* ey = (const float*)d_in[3];
    const float* W1 = (const float*)d_in[4];
    const float* b1 = (const float*)d_in[5];
    const float* W2 = (const float*)d_in[6];
    const float* b2 = (const float*)d_in[7];
    const float* W3 = (const float*)d_in[8];
    const float* b3 = (const float*)d_in[9];
    int n = in_sizes[0];
    int half = (n + 1) / 2;

    utgt_kernel<<<1, 64>>>(W1, b1, W2, b2, W3, b3);
    int blocks = (half + 127) / 128;
    netc_kernel<<<blocks, 128>>>(x, y, ex, ey, W1, b1, W2, b2, W3, b3,
                                 (float*)d_out, n, half);
}

// round 3
// speedup vs baseline: 1.3691x; 1.3691x over previous
#include <cuda_runtime.h>
#include <cstdint>

typedef unsigned long long u64;

__device__ float g_u_tgt;

// Compute u(target) = MLP(6.2562059, 6.2562059) once per launch.
__global__ void utgt_kernel(const float* __restrict__ W1, const float* __restrict__ b1,
                            const float* __restrict__ W2, const float* __restrict__ b2,
                            const float* __restrict__ W3, const float* __restrict__ b3) {
    __shared__ float h1[64];
    __shared__ float part[64];
    int t = threadIdx.x;  // 64 threads
    const float tt = 6.2562059f;
    float h = fmaf(W1[2 * t], tt, fmaf(W1[2 * t + 1], tt, b1[t]));
    h1[t] = fmaxf(h, 0.f);
    __syncthreads();
    float acc = b2[t];
#pragma unroll
    for (int k = 0; k < 64; k++) acc = fmaf(W2[t * 64 + k], h1[k], acc);
    part[t] = W3[t] * fmaxf(acc, 0.f);
    __syncthreads();
    if (t == 0) {
        float s = b3[0];
#pragma unroll
        for (int k = 0; k < 64; k++) s += part[k];
        g_u_tgt = s;
    }
}

__device__ __forceinline__ void hill_out(float* __restrict__ out, int n, int i,
                                         float xv, float yv, float u) {
    float xs = xv * 0.1f, ys = yv * 0.1f;
    float x2 = xs * xs, y2 = ys * ys;
    float ivx = 1.f / (0.25f + x2);
    float ivy = 1.f / (0.25f + y2);
    float hx = x2 * ivx, hy = y2 * ivy;
    float gx = 0.25f * ivx, gy = 0.25f * ivy;
    float dx = 10.f * (hx + 0.2f * gy - 1.1f * xs + u * hx);
    float dy = 10.f * (hy + 0.2f * gx - 1.1f * ys);
    out[i] = dx;
    out[n + i] = dy;
    out[2 * n + i] = -dx;
    out[3 * n + i] = -dy;
}

__device__ __forceinline__ u64 pack2(float lo, float hi) {
    return ((u64)__float_as_uint(hi) << 32) | (u64)__float_as_uint(lo);
}

__global__ void __launch_bounds__(128) netc_kernel(
    const float* __restrict__ x, const float* __restrict__ y,
    const float* __restrict__ ex, const float* __restrict__ ey,
    const float* __restrict__ W1, const float* __restrict__ b1,
    const float* __restrict__ W2, const float* __restrict__ b2,
    const float* __restrict__ W3, const float* __restrict__ b3,
    float* __restrict__ out, int n, int half) {
    __shared__ float w2s[64 * 64];  // raw W2, 16 KB (k-pairs naturally packed)
    __shared__ float w1s[128];
    __shared__ float b1s[64];
    __shared__ float b2s[64];
    __shared__ float w3s[64];

    int tid = threadIdx.x;
    for (int i = tid; i < 4096; i += 128) w2s[i] = W2[i];
    if (tid < 64) {
        b1s[tid] = b1[tid];
        b2s[tid] = b2[tid];
        w3s[tid] = W3[tid];
    }
    w1s[tid] = W1[tid];
    __syncthreads();

    int i0 = blockIdx.x * 128 + tid;
    if (i0 >= half) return;
    int i1 = i0 + half;
    bool has1 = (i1 < n);
    int i1c = has1 ? i1 : i0;

    float x0 = x[i0], y0 = y[i0];
    float a0 = x0 + ex[i0], c0 = y0 + ey[i0];
    float x1 = x[i1c], y1 = y[i1c];
    float a1 = x1 + ex[i1c], c1 = y1 + ey[i1c];

    // Layer 1. Pack h1 per element along k: h1pE[m] = (h[2m], h[2m+1]).
    u64 h1p0[32], h1p1[32];
#pragma unroll
    for (int m = 0; m < 32; m++) {
        int k0 = 2 * m, k1 = 2 * m + 1;
        float wA0 = w1s[2 * k0], wB0 = w1s[2 * k0 + 1], bb0 = b1s[k0];
        float wA1 = w1s[2 * k1], wB1 = w1s[2 * k1 + 1], bb1 = b1s[k1];
        float e0k0 = fmaxf(fmaf(wA0, a0, fmaf(wB0, c0, bb0)), 0.f);
        float e0k1 = fmaxf(fmaf(wA1, a0, fmaf(wB1, c0, bb1)), 0.f);
        float e1k0 = fmaxf(fmaf(wA0, a1, fmaf(wB0, c1, bb0)), 0.f);
        float e1k1 = fmaxf(fmaf(wA1, a1, fmaf(wB1, c1, bb1)), 0.f);
        h1p0[m] = pack2(e0k0, e0k1);
        h1p1[m] = pack2(e1k0, e1k1);
    }

    unsigned w2addr = (unsigned)__cvta_generic_to_shared(w2s);

    // Layer 2 + 3. Per output neuron j: one W2 row = 32 packed k-pairs, loaded
    // non-duplicated via LDS.128 (2 pairs per load). Each pair feeds one FFMA2
    // per element. Accumulators hold (even-k sum, odd-k sum).
    float o0 = 0.f, o1 = 0.f;
#pragma unroll 2
    for (int j = 0; j < 64; j++) {
        unsigned wrow = w2addr + (j << 8);  // 64 floats * 4 B per row
        u64 acc0a = 0ull, acc0b = 0ull, acc1a = 0ull, acc1b = 0ull;
#pragma unroll
        for (int m = 0; m < 32; m += 4) {
            u64 wa, wb, wc, wd;
            unsigned a = wrow + (m << 3);
            asm("ld.shared.v2.b64 {%0, %1}, [%2];"    : "=l"(wa), "=l"(wb) : "r"(a));
            asm("ld.shared.v2.b64 {%0, %1}, [%2+16];" : "=l"(wc), "=l"(wd) : "r"(a));
            asm("fma.rn.f32x2 %0, %1, %2, %0;" : "+l"(acc0a) : "l"(wa), "l"(h1p0[m + 0]));
            asm("fma.rn.f32x2 %0, %1, %2, %0;" : "+l"(acc1a) : "l"(wa), "l"(h1p1[m + 0]));
            asm("fma.rn.f32x2 %0, %1, %2, %0;" : "+l"(acc0b) : "l"(wb), "l"(h1p0[m + 1]));
            asm("fma.rn.f32x2 %0, %1, %2, %0;" : "+l"(acc1b) : "l"(wb), "l"(h1p1[m + 1]));
            asm("fma.rn.f32x2 %0, %1, %2, %0;" : "+l"(acc0a) : "l"(wc), "l"(h1p0[m + 2]));
            asm("fma.rn.f32x2 %0, %1, %2, %0;" : "+l"(acc1a) : "l"(wc), "l"(h1p1[m + 2]));
            asm("fma.rn.f32x2 %0, %1, %2, %0;" : "+l"(acc0b) : "l"(wd), "l"(h1p0[m + 3]));
            asm("fma.rn.f32x2 %0, %1, %2, %0;" : "+l"(acc1b) : "l"(wd), "l"(h1p1[m + 3]));
        }
        asm("add.rn.f32x2 %0, %0, %1;" : "+l"(acc0a) : "l"(acc0b));
        asm("add.rn.f32x2 %0, %0, %1;" : "+l"(acc1a) : "l"(acc1b));
        float bj = b2s[j];
        float s0 = __uint_as_float((unsigned)(acc0a & 0xffffffffu)) +
                   __uint_as_float((unsigned)(acc0a >> 32)) + bj;
        float s1 = __uint_as_float((unsigned)(acc1a & 0xffffffffu)) +
                   __uint_as_float((unsigned)(acc1a >> 32)) + bj;
        float w3 = w3s[j];
        o0 = fmaf(w3, fmaxf(s0, 0.f), o0);
        o1 = fmaf(w3, fmaxf(s1, 0.f), o1);
    }

    float bias3 = b3[0];
    float ut = g_u_tgt;
    float u0 = o0 + bias3 - ut;
    float u1 = o1 + bias3 - ut;

    hill_out(out, n, i0, x0, y0, u0);
    if (has1) hill_out(out, n, i1, x1, y1, u1);
}

extern "C" void kernel_launch(void* const* d_in, const int* in_sizes, int n_in,
                              void* d_out, int out_size) {
    const float* x  = (const float*)d_in[0];
    const float* y  = (const float*)d_in[1];
    const float* ex = (const float*)d_in[2];
    const float* ey = (const float*)d_in[3];
    const float* W1 = (const float*)d_in[4];
    const float* b1 = (const float*)d_in[5];
    const float* W2 = (const float*)d_in[6];
    const float* b2 = (const float*)d_in[7];
    const float* W3 = (const float*)d_in[8];
    const float* b3 = (const float*)d_in[9];
    int n = in_sizes[0];
    int half = (n + 1) / 2;

    utgt_kernel<<<1, 64>>>(W1, b1, W2, b2, W3, b3);
    int blocks = (half + 127) / 128;
    netc_kernel<<<blocks, 128>>>(x, y, ex, ey, W1, b1, W2, b2, W3, b3,
                                 (float*)d_out, n, half);
}

// round 5
// speedup vs baseline: 1.4215x; 1.0383x over previous
#include <cuda_runtime.h>
#include <cstdint>

typedef unsigned long long u64;

__device__ float g_u_tgt;

// Compute u(target) = MLP(6.2562059, 6.2562059) once per launch.
__global__ void utgt_kernel(const float* __restrict__ W1, const float* __restrict__ b1,
                            const float* __restrict__ W2, const float* __restrict__ b2,
                            const float* __restrict__ W3, const float* __restrict__ b3) {
    __shared__ float h1[64];
    __shared__ float part[64];
    int t = threadIdx.x;  // 64 threads
    const float tt = 6.2562059f;
    float h = fmaf(W1[2 * t], tt, fmaf(W1[2 * t + 1], tt, b1[t]));
    h1[t] = fmaxf(h, 0.f);
    __syncthreads();
    float acc = b2[t];
#pragma unroll
    for (int k = 0; k < 64; k++) acc = fmaf(W2[t * 64 + k], h1[k], acc);
    part[t] = W3[t] * fmaxf(acc, 0.f);
    __syncthreads();
    if (t == 0) {
        float s = b3[0];
#pragma unroll
        for (int k = 0; k < 64; k++) s += part[k];
        g_u_tgt = s;
    }
}

__device__ __forceinline__ void hill_out(float* __restrict__ out, int n, int i,
                                         float xv, float yv, float u) {
    float xs = xv * 0.1f, ys = yv * 0.1f;
    float x2 = xs * xs, y2 = ys * ys;
    float ivx = 1.f / (0.25f + x2);
    float ivy = 1.f / (0.25f + y2);
    float hx = x2 * ivx, hy = y2 * ivy;
    float gx = 0.25f * ivx, gy = 0.25f * ivy;
    float dx = 10.f * (hx + 0.2f * gy - 1.1f * xs + u * hx);
    float dy = 10.f * (hy + 0.2f * gx - 1.1f * ys);
    out[i] = dx;
    out[n + i] = dy;
    out[2 * n + i] = -dx;
    out[3 * n + i] = -dy;
}

__device__ __forceinline__ u64 pack2(float lo, float hi) {
    return ((u64)__float_as_uint(hi) << 32) | (u64)__float_as_uint(lo);
}

__global__ void __launch_bounds__(128, 3) netc_kernel(
    const float* __restrict__ x, const float* __restrict__ y,
    const float* __restrict__ ex, const float* __restrict__ ey,
    const float* __restrict__ W1, const float* __restrict__ b1,
    const float* __restrict__ W2, const float* __restrict__ b2,
    const float* __restrict__ W3, const float* __restrict__ b3,
    float* __restrict__ out, int n, int half) {
    __shared__ float w2s[64 * 64];  // raw W2, 16 KB (k-pairs naturally packed)
    __shared__ float w1s[128];
    __shared__ float b1s[64];
    __shared__ float b2s[64];
    __shared__ float w3s[64];

    int tid = threadIdx.x;
    for (int i = tid; i < 4096; i += 128) w2s[i] = W2[i];
    if (tid < 64) {
        b1s[tid] = b1[tid];
        b2s[tid] = b2[tid];
        w3s[tid] = W3[tid];
    }
    w1s[tid] = W1[tid];
    __syncthreads();

    int i0 = blockIdx.x * 128 + tid;
    if (i0 >= half) return;
    int i1 = i0 + half;
    bool has1 = (i1 < n);
    int i1c = has1 ? i1 : i0;

    // Inputs for layer 1 only; x/y reloaded at epilogue to cut live registers.
    float a0 = x[i0] + ex[i0], c0 = y[i0] + ey[i0];
    float a1 = x[i1c] + ex[i1c], c1 = y[i1c] + ey[i1c];

    // Layer 1. Pack h1 per element along k: h1pE[m] = (h[2m], h[2m+1]).
    u64 h1p0[32], h1p1[32];
#pragma unroll
    for (int m = 0; m < 32; m++) {
        int k0 = 2 * m, k1 = 2 * m + 1;
        float wA0 = w1s[2 * k0], wB0 = w1s[2 * k0 + 1], bb0 = b1s[k0];
        float wA1 = w1s[2 * k1], wB1 = w1s[2 * k1 + 1], bb1 = b1s[k1];
        float e0k0 = fmaxf(fmaf(wA0, a0, fmaf(wB0, c0, bb0)), 0.f);
        float e0k1 = fmaxf(fmaf(wA1, a0, fmaf(wB1, c0, bb1)), 0.f);
        float e1k0 = fmaxf(fmaf(wA0, a1, fmaf(wB0, c1, bb0)), 0.f);
        float e1k1 = fmaxf(fmaf(wA1, a1, fmaf(wB1, c1, bb1)), 0.f);
        h1p0[m] = pack2(e0k0, e0k1);
        h1p1[m] = pack2(e1k0, e1k1);
    }

    unsigned w2addr = (unsigned)__cvta_generic_to_shared(w2s);

    // Layer 2 + 3. Per output neuron j: one W2 row = 32 packed k-pairs, loaded
    // non-duplicated via LDS.128 (2 pairs per load). Each pair feeds one FFMA2
    // per element. Accumulators hold (even-k sum, odd-k sum).
    float o0 = 0.f, o1 = 0.f;
#pragma unroll 2
    for (int j = 0; j < 64; j++) {
        unsigned wrow = w2addr + (j << 8);  // 64 floats * 4 B per row
        u64 acc0a = 0ull, acc0b = 0ull, acc1a = 0ull, acc1b = 0ull;
#pragma unroll
        for (int m = 0; m < 32; m += 4) {
            u64 wa, wb, wc, wd;
            unsigned a = wrow + (m << 3);
            asm("ld.shared.v2.b64 {%0, %1}, [%2];"    : "=l"(wa), "=l"(wb) : "r"(a));
            asm("ld.shared.v2.b64 {%0, %1}, [%2+16];" : "=l"(wc), "=l"(wd) : "r"(a));
            asm("fma.rn.f32x2 %0, %1, %2, %0;" : "+l"(acc0a) : "l"(wa), "l"(h1p0[m + 0]));
            asm("fma.rn.f32x2 %0, %1, %2, %0;" : "+l"(acc1a) : "l"(wa), "l"(h1p1[m + 0]));
            asm("fma.rn.f32x2 %0, %1, %2, %0;" : "+l"(acc0b) : "l"(wb), "l"(h1p0[m + 1]));
            asm("fma.rn.f32x2 %0, %1, %2, %0;" : "+l"(acc1b) : "l"(wb), "l"(h1p1[m + 1]));
            asm("fma.rn.f32x2 %0, %1, %2, %0;" : "+l"(acc0a) : "l"(wc), "l"(h1p0[m + 2]));
            asm("fma.rn.f32x2 %0, %1, %2, %0;" : "+l"(acc1a) : "l"(wc), "l"(h1p1[m + 2]));
            asm("fma.rn.f32x2 %0, %1, %2, %0;" : "+l"(acc0b) : "l"(wd), "l"(h1p0[m + 3]));
            asm("fma.rn.f32x2 %0, %1, %2, %0;" : "+l"(acc1b) : "l"(wd), "l"(h1p1[m + 3]));
        }
        asm("add.rn.f32x2 %0, %0, %1;" : "+l"(acc0a) : "l"(acc0b));
        asm("add.rn.f32x2 %0, %0, %1;" : "+l"(acc1a) : "l"(acc1b));
        float bj = b2s[j];
        float s0 = __uint_as_float((unsigned)(acc0a & 0xffffffffu)) +
                   __uint_as_float((unsigned)(acc0a >> 32)) + bj;
        float s1 = __uint_as_float((unsigned)(acc1a & 0xffffffffu)) +
                   __uint_as_float((unsigned)(acc1a >> 32)) + bj;
        float w3 = w3s[j];
        o0 = fmaf(w3, fmaxf(s0, 0.f), o0);
        o1 = fmaf(w3, fmaxf(s1, 0.f), o1);
    }

    float bias3 = b3[0];
    float ut = g_u_tgt;
    float u0 = o0 + bias3 - ut;
    float u1 = o1 + bias3 - ut;

    // Reload x/y (L2-resident) for the hill epilogue.
    hill_out(out, n, i0, x[i0], y[i0], u0);
    if (has1) hill_out(out, n, i1, x[i1], y[i1], u1);
}

extern "C" void kernel_launch(void* const* d_in, const int* in_sizes, int n_in,
                              void* d_out, int out_size) {
    const float* x  = (const float*)d_in[0];
    const float* y  = (const float*)d_in[1];
    const float* ex = (const float*)d_in[2];
    const float* ey = (const float*)d_in[3];
    const float* W1 = (const float*)d_in[4];
    const float* b1 = (const float*)d_in[5];
    const float* W2 = (const float*)d_in[6];
    const float* b2 = (const float*)d_in[7];
    const float* W3 = (const float*)d_in[8];
    const float* b3 = (const float*)d_in[9];
    int n = in_sizes[0];
    int half = (n + 1) / 2;

    utgt_kernel<<<1, 64>>>(W1, b1, W2, b2, W3, b3);
    int blocks = (half + 127) / 128;
    netc_kernel<<<blocks, 128>>>(x, y, ex, ey, W1, b1, W2, b2, W3, b3,
                                 (float*)d_out, n, half);
}